// round 1
// baseline (speedup 1.0000x reference)
#include <cuda_runtime.h>
#include <cuda_bf16.h>
#include <math.h>

// Problem constants
#define BB 32
#define TT 2048
#define HH 512
#define UU 32
#define ROWS (BB * TT)   // 65536

// ---------------- scratch (no allocations allowed) ----------------
__device__ float g_delta[(size_t)ROWS * UU];   // 8 MB
__device__ float g_sum[BB * HH];               // per-(b,h) sum of exp
__device__ float g_inv[BB * HH];

// ---------------- f32x2 helpers (FFMA2 only reachable via PTX) ----------------
__device__ __forceinline__ unsigned long long pack2(float lo, float hi) {
    unsigned long long r;
    asm("mov.b64 %0, {%1, %2};" : "=l"(r) : "f"(lo), "f"(hi));
    return r;
}
__device__ __forceinline__ float2 unpack2(unsigned long long v) {
    float2 f;
    asm("mov.b64 {%0, %1}, %2;" : "=f"(f.x), "=f"(f.y) : "l"(v));
    return f;
}
__device__ __forceinline__ void ffma2(unsigned long long& d, unsigned long long a, unsigned long long b) {
    asm("fma.rn.f32x2 %0, %1, %2, %3;" : "=l"(d) : "l"(a), "l"(b), "l"(d));
}

// =====================================================================
// K0: zero the per-(b,h) exp-sum accumulator (re-run every graph replay)
// =====================================================================
__global__ void k_zero() {
    int i = blockIdx.x * 256 + threadIdx.x;
    if (i < BB * HH) g_sum[i] = 0.0f;
}

// =====================================================================
// K1: delta[row, u] = lambd[t]*tanh(x@Wx + bx) + (1-lambd)*tanh(t@Wt + bt)
// Warp per 8 rows, lane = u. Packed (x,t) x (Wx,Wt) via FFMA2 computes both
// GEMMs in one instruction stream.
// smem: packed weights [512][32] float2 (128KB) + per-warp staging (32KB)
// =====================================================================
#define K1_SMEM (HH * UU * 8 + 8 * 8 * 64 * 8)   // 131072 + 32768 = 163840

__global__ void __launch_bounds__(256, 1)
k_delta(const float* __restrict__ x, const float* __restrict__ t,
        const float* __restrict__ kx, const float* __restrict__ kt,
        const float* __restrict__ bx, const float* __restrict__ bt,
        const float* __restrict__ lambd) {
    extern __shared__ char smem[];
    float2* swxt = (float2*)smem;  // [h][u] packed (wx, wt)
    unsigned long long* sxt = (unsigned long long*)(smem + (size_t)HH * UU * 8);

    const int tid = threadIdx.x;
    const int lane = tid & 31;
    const int w = tid >> 5;

    // load + interleave weights (both are [H][U] row-major, same linear index)
    for (int i = tid; i < HH * UU; i += 256)
        swxt[i] = make_float2(kx[i], kt[i]);
    __syncthreads();

    const float biasx = bx[lane];
    const float biast = bt[lane];

    const int rowBase = blockIdx.x * 64 + w * 8;

    unsigned long long acc[8];
#pragma unroll
    for (int r = 0; r < 8; r++) acc[r] = 0ull;

    unsigned long long* mystage = sxt + w * (8 * 64);
    const unsigned long long* wbase = (const unsigned long long*)smem;

    for (int c = 0; c < 8; c++) {
        // stage packed (x,t) chunk: 8 rows x 64 h
#pragma unroll
        for (int r = 0; r < 8; r++) {
            const size_t off = (size_t)(rowBase + r) * HH + c * 64 + lane * 2;
            const float2 xv = *(const float2*)(x + off);
            const float2 tv = *(const float2*)(t + off);
            mystage[r * 64 + lane * 2 + 0] = pack2(xv.x, tv.x);
            mystage[r * 64 + lane * 2 + 1] = pack2(xv.y, tv.y);
        }
        __syncwarp();

        const unsigned long long* wp = wbase + (c * 64) * UU + lane;
#pragma unroll 8
        for (int h = 0; h < 64; h++) {
            const unsigned long long wv = wp[h * UU];
#pragma unroll
            for (int r = 0; r < 8; r++)
                ffma2(acc[r], mystage[r * 64 + h], wv);
        }
        __syncwarp();
    }

#pragma unroll
    for (int r = 0; r < 8; r++) {
        const int row = rowBase + r;
        const float2 gb = unpack2(acc[r]);
        const float gamma = tanhf(gb.x + biasx);
        const float beta  = tanhf(gb.y + biast);
        const float lam = __ldg(lambd + (row & (TT - 1)));
        g_delta[(size_t)row * UU + lane] = lam * gamma + (1.0f - lam) * beta;
    }
}

// =====================================================================
// K2: e = exp(delta @ Wa) written to d_out; per-(b,h) partial sums of e
// reduced in-block then atomicAdd'ed to g_sum. Max-subtraction skipped:
// |score| <= U * max|Wa| * max|delta| ~ 3.4, exp is safe.
// =====================================================================
#define K2_SMEM (UU * 256 * 8 + HH * 4)   // 65536 + 2048 = 67584

__global__ void __launch_bounds__(256, 1)
k_scores(const float* __restrict__ ka, float* __restrict__ out) {
    extern __shared__ char smem[];
    unsigned long long* sWa2 = (unsigned long long*)smem;  // [u][256] pairs (h even/odd)
    float* ssum = (float*)(smem + (size_t)UU * 256 * 8);

    const int tid = threadIdx.x;
    const int lane = tid & 31;
    const int w = tid >> 5;

    for (int i = tid; i < UU * 256; i += 256) {
        const int u = i >> 8, p = i & 255;
        sWa2[i] = pack2(ka[u * HH + 2 * p], ka[u * HH + 2 * p + 1]);
    }
    for (int i = tid; i < HH; i += 256) ssum[i] = 0.0f;
    __syncthreads();

    const int rowBase = blockIdx.x * 64 + w * 8;

    float s0[8], s1[8];
#pragma unroll
    for (int j = 0; j < 8; j++) { s0[j] = 0.0f; s1[j] = 0.0f; }

    for (int r = 0; r < 8; r++) {
        const int row = rowBase + r;
        const float dval = g_delta[(size_t)row * UU + lane];

        unsigned long long acc[8];
#pragma unroll
        for (int j = 0; j < 8; j++) acc[j] = 0ull;

#pragma unroll 8
        for (int u = 0; u < UU; u++) {
            const float du = __shfl_sync(0xffffffffu, dval, u);
            const unsigned long long dd = pack2(du, du);
            const unsigned long long* wap = sWa2 + u * 256 + lane;
#pragma unroll
            for (int j = 0; j < 8; j++)
                ffma2(acc[j], wap[j * 32], dd);
        }

        float* orow = out + (size_t)row * HH;
#pragma unroll
        for (int j = 0; j < 8; j++) {
            const float2 v = unpack2(acc[j]);
            const float e0 = __expf(v.x);
            const float e1 = __expf(v.y);
            const int h0 = (j * 32 + lane) * 2;
            *(float2*)(orow + h0) = make_float2(e0, e1);
            s0[j] += e0;
            s1[j] += e1;
        }
    }

    // block reduction of exp-sums
#pragma unroll
    for (int j = 0; j < 8; j++) {
        const int h0 = (j * 32 + lane) * 2;
        atomicAdd(&ssum[h0], s0[j]);
        atomicAdd(&ssum[h0 + 1], s1[j]);
    }
    __syncthreads();

    const int b = blockIdx.x >> 5;  // 32 blocks per batch (64 rows/block, T=2048)
    for (int i = tid; i < HH; i += 256)
        atomicAdd(&g_sum[b * HH + i], ssum[i]);
}

// =====================================================================
// K2b: reciprocal of column sums
// =====================================================================
__global__ void k_inv() {
    int i = blockIdx.x * 256 + threadIdx.x;
    if (i < BB * HH) g_inv[i] = 1.0f / g_sum[i];
}

// =====================================================================
// K3: alpha = e * inv[b,h]  (in-place on d_out, float4)
// =====================================================================
__global__ void __launch_bounds__(256)
k_norm(float* __restrict__ out) {
    const size_t i4 = (size_t)blockIdx.x * 256 + threadIdx.x;
    float4 e = ((float4*)out)[i4];
    const size_t i = i4 * 4;
    const int h = (int)(i & (size_t)(HH - 1));
    const int b = (int)(i >> 20);  // T*H = 2^20
    const float4 inv = *(const float4*)(g_inv + b * HH + h);
    e.x *= inv.x; e.y *= inv.y; e.z *= inv.z; e.w *= inv.w;
    ((float4*)out)[i4] = e;
}

// =====================================================================
extern "C" void kernel_launch(void* const* d_in, const int* in_sizes, int n_in,
                              void* d_out, int out_size) {
    const float* x     = (const float*)d_in[0];
    const float* t     = (const float*)d_in[1];
    const float* kx    = (const float*)d_in[2];
    const float* kt    = (const float*)d_in[3];
    const float* ka    = (const float*)d_in[4];
    const float* bx    = (const float*)d_in[5];
    const float* bt    = (const float*)d_in[6];
    const float* lambd = (const float*)d_in[7];
    float* out = (float*)d_out;

    // idempotent, host-side only (not a stream op) — legal under capture
    cudaFuncSetAttribute(k_delta, cudaFuncAttributeMaxDynamicSharedMemorySize, K1_SMEM);
    cudaFuncSetAttribute(k_scores, cudaFuncAttributeMaxDynamicSharedMemorySize, K2_SMEM);

    k_zero<<<64, 256>>>();
    k_delta<<<ROWS / 64, 256, K1_SMEM>>>(x, t, kx, kt, bx, bt, lambd);
    k_scores<<<ROWS / 64, 256, K2_SMEM>>>(ka, out);
    k_inv<<<64, 256>>>();
    k_norm<<<(ROWS * HH) / 4 / 256, 256>>>(out);
}